// round 16
// baseline (speedup 1.0000x reference)
#include <cuda_runtime.h>
#include <cuda_bf16.h>
#include <cstdint>
#include <math.h>

#define NT      262144      // total nodes (512 subgraphs x 512 nodes)
#define NN      512         // nodes per subgraph / original graph
#define E_SUB   2097152     // edges in union-of-subgraphs graph
#define EO      8192        // edges in original graph
#define D       64          // emb dim
#define LAYERS  4

// ---- mma tile smem layout (word == uint32 == 2 bf16) ----
#define AP      36                      // word pitch for A rows (conflict-free)
#define AW_WORDS (128 * AP)             // 4608 words per A sub-tile
#define WW_WORDS (64 * AP)              // 2304 words per W sub-tile
#define SMO_BIAS ((4 * AW_WORDS + 4 * WW_WORDS) * 4)   // 110592
#define SM_MMA_BYTES (SMO_BIAS + 256)                  // 110848

// ---- split storage: per channel-pair q: uint2{ hi=bf16x2(c2q,c2q+1), lo } --
// A row = 32 uint2 = 16 uint4; identical byte count to fp32.

// ------------------------- device scratch (no cudaMalloc allowed) ----------
__device__ __align__(16) uint4 g_hX[(size_t)NT * 16];    // split(x)
__device__ __align__(16) uint4 g_hA[(size_t)NT * 16];    // split h (ping)
__device__ __align__(16) uint4 g_hB[(size_t)NT * 16];    // split h (pong)
__device__ __align__(16) uint4 g_agg[(size_t)NT * 16];   // split agg
__device__ __align__(16) float g_Y[(size_t)NT * D];

__device__ __align__(16) uint4 g_wsplit[LAYERS * 2 * 64 * 16]; // pre-split W

__device__ __align__(16) float g_xpart[16 * NN * D];     // xsum partials
__device__ __align__(16) float g_aggsB[LAYERS * NN * D]; // per-layer small agg
__device__ __align__(16) float g_y2[NN * D];

__device__ __align__(16) float g_stAB[LAYERS * 2 * D];
__device__ __align__(16) float g_stSB[LAYERS * 2 * D];

__device__ int g_cnt[NT];
__device__ int g_rowptr[NT + 1];
__device__ int g_bsum[256];
__device__ int g_csrsrc[E_SUB];

// ------------------------- CSR build ---------------------------------------
__global__ void k_hist(const int* __restrict__ dst) {
    int e = blockIdx.x * blockDim.x + threadIdx.x;
    if (e < E_SUB) atomicAdd(&g_cnt[dst[e]], 1);
}

__global__ void k_bsum() {
    __shared__ int sh[256];
    int b = blockIdx.x, t = threadIdx.x;
    int base = b * 1024 + t * 4;
    int v = g_cnt[base] + g_cnt[base + 1] + g_cnt[base + 2] + g_cnt[base + 3];
    sh[t] = v;
    __syncthreads();
    for (int off = 128; off > 0; off >>= 1) {
        if (t < off) sh[t] += sh[t + off];
        __syncthreads();
    }
    if (t == 0) g_bsum[b] = sh[0];
}

__global__ void k_scanb() {
    __shared__ int sh[256];
    int t = threadIdx.x;
    int orig = g_bsum[t];
    sh[t] = orig;
    __syncthreads();
    for (int off = 1; off < 256; off <<= 1) {
        int v = (t >= off) ? sh[t - off] : 0;
        __syncthreads();
        sh[t] += v;
        __syncthreads();
    }
    g_bsum[t] = sh[t] - orig;   // exclusive
}

__global__ void k_scanlocal() {
    __shared__ int sh[256];
    int b = blockIdx.x, t = threadIdx.x;
    int base = (b * 256 + t) * 4;
    int c0 = g_cnt[base], c1 = g_cnt[base + 1], c2 = g_cnt[base + 2], c3 = g_cnt[base + 3];
    int tsum = c0 + c1 + c2 + c3;
    sh[t] = tsum;
    __syncthreads();
    for (int off = 1; off < 256; off <<= 1) {
        int v = (t >= off) ? sh[t - off] : 0;
        __syncthreads();
        sh[t] += v;
        __syncthreads();
    }
    int excl = sh[t] - tsum + g_bsum[b];
    int e0 = excl, e1 = e0 + c0, e2 = e1 + c1, e3 = e2 + c2;
    g_rowptr[base] = e0; g_rowptr[base + 1] = e1;
    g_rowptr[base + 2] = e2; g_rowptr[base + 3] = e3;
    g_cnt[base] = e0; g_cnt[base + 1] = e1;
    g_cnt[base + 2] = e2; g_cnt[base + 3] = e3;
    if (b == 255 && t == 255) g_rowptr[NT] = E_SUB;
}

__global__ void k_scatter(const int* __restrict__ src, const int* __restrict__ dst) {
    int e = blockIdx.x * blockDim.x + threadIdx.x;
    if (e < E_SUB) {
        int pos = atomicAdd(&g_cnt[dst[e]], 1);
        g_csrsrc[pos] = src[e];
    }
}

// ---------------- bf16 split helpers ----------------------------------------
__device__ __forceinline__ void split2(float x, float y, uint32_t& hi, uint32_t& lo) {
    __nv_bfloat16 hx = __float2bfloat16_rn(x);
    __nv_bfloat16 hy = __float2bfloat16_rn(y);
    __nv_bfloat162 hp = __halves2bfloat162(hx, hy);          // low half = x
    hi = *reinterpret_cast<uint32_t*>(&hp);
    __nv_bfloat162 lp = __floats2bfloat162_rn(
        x - __bfloat162float(hx), y - __bfloat162float(hy));
    lo = *reinterpret_cast<uint32_t*>(&lp);
}

__device__ __forceinline__ float2 unsplit(uint2 u) {
    __nv_bfloat162 hb = *reinterpret_cast<__nv_bfloat162*>(&u.x);
    __nv_bfloat162 lb = *reinterpret_cast<__nv_bfloat162*>(&u.y);
    float2 hf = __bfloat1622float2(hb);
    float2 lf = __bfloat1622float2(lb);
    return make_float2(hf.x + lf.x, hf.y + lf.y);
}

__device__ __forceinline__ void mma_bf16(float* c, uint32_t a0, uint32_t a1,
                                         uint32_t a2, uint32_t a3,
                                         uint32_t b0, uint32_t b1) {
    asm volatile(
        "mma.sync.aligned.m16n8k16.row.col.f32.bf16.bf16.f32 "
        "{%0,%1,%2,%3}, {%4,%5,%6,%7}, {%8,%9}, {%0,%1,%2,%3};"
        : "+f"(c[0]), "+f"(c[1]), "+f"(c[2]), "+f"(c[3])
        : "r"(a0), "r"(a1), "r"(a2), "r"(a3), "r"(b0), "r"(b1));
}

// ------------------------- prologue conversions -----------------------------
// split x: fp32 [NT][64] -> uint4 per 4 channels (hi01, lo01, hi23, lo23)
__global__ void k_split_x(const float* __restrict__ x) {
    int task = blockIdx.x * blockDim.x + threadIdx.x;     // < NT*16
    float4 v = reinterpret_cast<const float4*>(x)[task];
    uint32_t h0, l0, h1, l1;
    split2(v.x, v.y, h0, l0);
    split2(v.z, v.w, h1, l1);
    g_hX[task] = make_uint4(h0, l0, h1, l1);
}

// split all W matrices once: layout [l][p][row 64][16 uint4]
__global__ void k_wconv(const float* __restrict__ Wrel, const float* __restrict__ Wroot) {
    int task = blockIdx.x * blockDim.x + threadIdx.x;     // < LAYERS*2*64*16
    int f = task & 15, r = (task >> 4) & 63;
    int p = (task >> 10) & 1, l = task >> 11;
    const float* W = (p ? Wroot : Wrel) + l * 4096;
    float4 v = reinterpret_cast<const float4*>(W)[r * 16 + f];
    uint32_t h0, l0, h1, l1;
    split2(v.x, v.y, h0, l0);
    split2(v.z, v.w, h1, l1);
    g_wsplit[task] = make_uint4(h0, l0, h1, l1);
}

// ------------------------- edge aggregation (split in/out) ------------------
__global__ void k_gather(const uint4* __restrict__ h) {
    int gw = (blockIdx.x * blockDim.x + threadIdx.x) >> 5;
    int lane = threadIdx.x & 31;
    if (gw >= NT) return;
    int s = g_rowptr[gw], e = g_rowptr[gw + 1];
    const uint2* h2 = reinterpret_cast<const uint2*>(h);
    float2 a = make_float2(0.f, 0.f), b = make_float2(0.f, 0.f);
    int i = s;
    for (; i + 1 < e; i += 2) {
        int s0 = g_csrsrc[i], s1 = g_csrsrc[i + 1];
        float2 v0 = unsplit(h2[(size_t)s0 * 32 + lane]);
        float2 v1 = unsplit(h2[(size_t)s1 * 32 + lane]);
        a.x += v0.x; a.y += v0.y;
        b.x += v1.x; b.y += v1.y;
    }
    if (i < e) {
        int s0 = g_csrsrc[i];
        float2 v0 = unsplit(h2[(size_t)s0 * 32 + lane]);
        a.x += v0.x; a.y += v0.y;
    }
    uint32_t hi, lo;
    split2(a.x + b.x, a.y + b.y, hi, lo);
    reinterpret_cast<uint2*>(g_agg)[(size_t)gw * 32 + lane] = make_uint2(hi, lo);
}

// -------- big dual GEMM on tensor cores (pre-split operands) ----------------
__global__ void __launch_bounds__(256, 2)
k_gemm_mma(const uint4* __restrict__ A0, const uint4* __restrict__ A1,
           const uint4* __restrict__ Wp,       // [2][64][16] pre-split
           const float* __restrict__ bias, float* __restrict__ Y,
           float* __restrict__ st) {
    extern __shared__ char smem[];
    uint32_t* Aw = reinterpret_cast<uint32_t*>(smem);             // Ah0 Al0 Ah1 Al1
    uint32_t* Ww = Aw + 4 * AW_WORDS;                             // Wh0 Wl0 Wh1 Wl1
    float* bias_s = reinterpret_cast<float*>(smem + SMO_BIAS);

    int t = threadIdx.x;
    int w = t >> 5, lane = t & 31;
    int g = lane >> 2, tg = lane & 3;
    int row0 = blockIdx.x * 128;

    if (t < 64) bias_s[t] = bias[t];

    // ---- A tiles: pre-split, pure copy into pitched smem ----
    for (int p = 0; p < 2; p++) {
        const uint4* src = (p ? A1 : A0) + (size_t)row0 * 16;
        uint32_t* hb = Aw + (2 * p) * AW_WORDS;
        uint32_t* lb = hb + AW_WORDS;
#pragma unroll
        for (int it = 0; it < 8; it++) {
            int task = it * 256 + t;        // 2048 tasks = 128 rows x 16 uint4
            int r = task >> 4, f = task & 15;
            uint4 v = src[r * 16 + f];
            hb[r * AP + 2 * f]     = v.x;
            lb[r * AP + 2 * f]     = v.y;
            hb[r * AP + 2 * f + 1] = v.z;
            lb[r * AP + 2 * f + 1] = v.w;
        }
    }
    // ---- W tiles: pre-split ----
    for (int p = 0; p < 2; p++) {
        const uint4* src = Wp + p * 1024;
        uint32_t* hb = Ww + (2 * p) * WW_WORDS;
        uint32_t* lb = hb + WW_WORDS;
#pragma unroll
        for (int it = 0; it < 4; it++) {
            int task = it * 256 + t;        // 1024 tasks = 64 rows x 16 uint4
            int r = task >> 4, f = task & 15;
            uint4 v = src[r * 16 + f];
            hb[r * AP + 2 * f]     = v.x;
            lb[r * AP + 2 * f]     = v.y;
            hb[r * AP + 2 * f + 1] = v.z;
            lb[r * AP + 2 * f + 1] = v.w;
        }
    }
    __syncthreads();

    // ---- warp tile: 16 rows x 64 cols; acc[j] = m16n8 fragment ----
    float acc[8][4];
#pragma unroll
    for (int j = 0; j < 8; j++)
#pragma unroll
        for (int i = 0; i < 4; i++) acc[j][i] = 0.f;

    int ra = (w * 16 + g) * AP;
    int rb = (w * 16 + g + 8) * AP;

#pragma unroll
    for (int p = 0; p < 2; p++) {
        const uint32_t* Ah_ = Aw + (2 * p) * AW_WORDS;
        const uint32_t* Al_ = Ah_ + AW_WORDS;
        const uint32_t* Wh_ = Ww + (2 * p) * WW_WORDS;
        const uint32_t* Wl_ = Wh_ + WW_WORDS;
#pragma unroll
        for (int ks = 0; ks < 4; ks++) {
            int o = ks * 8 + tg;
            uint32_t ah0 = Ah_[ra + o],     ah1 = Ah_[rb + o];
            uint32_t ah2 = Ah_[ra + o + 4], ah3 = Ah_[rb + o + 4];
            uint32_t al0 = Al_[ra + o],     al1 = Al_[rb + o];
            uint32_t al2 = Al_[ra + o + 4], al3 = Al_[rb + o + 4];
#pragma unroll
            for (int j = 0; j < 8; j++) {
                int wb = (j * 8 + g) * AP + o;
                uint32_t bh0 = Wh_[wb], bh1 = Wh_[wb + 4];
                uint32_t bl0 = Wl_[wb], bl1 = Wl_[wb + 4];
                mma_bf16(acc[j], ah0, ah1, ah2, ah3, bh0, bh1);
                mma_bf16(acc[j], al0, al1, al2, al3, bh0, bh1);
                mma_bf16(acc[j], ah0, ah1, ah2, ah3, bl0, bl1);
            }
        }
    }

    // ---- epilogue: bias, write Y, BN stat partials ----
    float ps0[8], ps1[8], pq0[8], pq1[8];
    int r0g = row0 + w * 16 + g;
#pragma unroll
    for (int j = 0; j < 8; j++) {
        int c0 = j * 8 + 2 * tg;
        float b0 = bias_s[c0], b1 = bias_s[c0 + 1];
        float y00 = acc[j][0] + b0, y01 = acc[j][1] + b1;
        float y10 = acc[j][2] + b0, y11 = acc[j][3] + b1;
        *reinterpret_cast<float2*>(&Y[(size_t)r0g * D + c0]) = make_float2(y00, y01);
        *reinterpret_cast<float2*>(&Y[(size_t)(r0g + 8) * D + c0]) = make_float2(y10, y11);
        ps0[j] = y00 + y10; ps1[j] = y01 + y11;
        pq0[j] = y00 * y00 + y10 * y10;
        pq1[j] = y01 * y01 + y11 * y11;
    }

    __syncthreads();                                  // smem A/W now free
    float* redS = reinterpret_cast<float*>(smem);     // [64][72]
    float* redQ = redS + 64 * 72;
    int grp = w * 8 + g;
#pragma unroll
    for (int j = 0; j < 8; j++) {
        int c0 = j * 8 + 2 * tg;
        *reinterpret_cast<float2*>(&redS[grp * 72 + c0]) = make_float2(ps0[j], ps1[j]);
        *reinterpret_cast<float2*>(&redQ[grp * 72 + c0]) = make_float2(pq0[j], pq1[j]);
    }
    __syncthreads();
    if (t < 64) {
        float s = 0.f, q = 0.f;
#pragma unroll 4
        for (int k = 0; k < 64; k++) {
            s += redS[k * 72 + t];
            q += redQ[k * 72 + t];
        }
        atomicAdd(&st[t], s);
        atomicAdd(&st[64 + t], q);
    }
}

// ------------------------- small dual GEMM (scalar, fused stats) ------------
// A1 = sum of the 16 xsum partials in g_xpart.
__global__ void __launch_bounds__(256)
k_gemmR(const float* __restrict__ A0,
        const float* __restrict__ W0, const float* __restrict__ W1v,
        const float* __restrict__ bias, float* __restrict__ Y,
        float* __restrict__ st) {
    __shared__ __align__(16) float sA[64][65];
    __shared__ __align__(16) float sW[64][68];
    int t  = threadIdx.x;
    int tx = t & 15, ty = t >> 4;
    int row0 = blockIdx.x * 64;
    int cc = t & 63, rb = t >> 6;

    float acc[4][4];
#pragma unroll
    for (int i = 0; i < 4; i++)
#pragma unroll
        for (int j = 0; j < 4; j++) acc[i][j] = 0.f;

    for (int p = 0; p < 2; p++) {
        const float* W = p ? W1v : W0;
#pragma unroll
        for (int j = 0; j < 16; j++) {
            int r = rb + j * 4;
            float a;
            if (p == 0) {
                a = A0[(size_t)(row0 + r) * D + cc];
            } else {
                a = 0.f;
#pragma unroll
                for (int q16 = 0; q16 < 16; q16++)
                    a += g_xpart[q16 * NN * D + (row0 + r) * D + cc];
            }
            sA[cc][r] = a;
        }
#pragma unroll
        for (int j = 0; j < 16; j++) {
            int ci = rb + j * 4;
            sW[cc][ci] = W[ci * D + cc];
        }
        __syncthreads();
#pragma unroll
        for (int k = 0; k < 64; k++) {
            float4 bv = *reinterpret_cast<const float4*>(&sW[k][tx * 4]);
            float a0 = sA[k][ty * 4 + 0];
            float a1 = sA[k][ty * 4 + 1];
            float a2 = sA[k][ty * 4 + 2];
            float a3 = sA[k][ty * 4 + 3];
            acc[0][0] += a0 * bv.x; acc[0][1] += a0 * bv.y; acc[0][2] += a0 * bv.z; acc[0][3] += a0 * bv.w;
            acc[1][0] += a1 * bv.x; acc[1][1] += a1 * bv.y; acc[1][2] += a1 * bv.z; acc[1][3] += a1 * bv.w;
            acc[2][0] += a2 * bv.x; acc[2][1] += a2 * bv.y; acc[2][2] += a2 * bv.z; acc[2][3] += a2 * bv.w;
            acc[3][0] += a3 * bv.x; acc[3][1] += a3 * bv.y; acc[3][2] += a3 * bv.z; acc[3][3] += a3 * bv.w;
        }
        __syncthreads();
    }

    float4 bb = *reinterpret_cast<const float4*>(&bias[tx * 4]);
    float bcol[4] = { bb.x, bb.y, bb.z, bb.w };
    float ls[4] = {0.f, 0.f, 0.f, 0.f};
    float lq[4] = {0.f, 0.f, 0.f, 0.f};
#pragma unroll
    for (int jr = 0; jr < 4; jr++) {
        float y0 = acc[jr][0] + bcol[0];
        float y1 = acc[jr][1] + bcol[1];
        float y2 = acc[jr][2] + bcol[2];
        float y3 = acc[jr][3] + bcol[3];
        ls[0] += y0; ls[1] += y1; ls[2] += y2; ls[3] += y3;
        lq[0] += y0 * y0; lq[1] += y1 * y1; lq[2] += y2 * y2; lq[3] += y3 * y3;
        int r = row0 + ty * 4 + jr;
        *reinterpret_cast<float4*>(&Y[(size_t)r * D + tx * 4]) =
            make_float4(y0, y1, y2, y3);
    }

    float* rs = &sA[0][0];
    float* rq = rs + 1024;
#pragma unroll
    for (int j = 0; j < 4; j++) {
        rs[ty * 64 + tx * 4 + j] = ls[j];
        rq[ty * 64 + tx * 4 + j] = lq[j];
    }
    __syncthreads();
    if (t < 64) {
        float s = 0.f, q = 0.f;
#pragma unroll
        for (int g = 0; g < 16; g++) {
            s += rs[g * 64 + t];
            q += rq[g * 64 + t];
        }
        atomicAdd(&st[t], s);
        atomicAdd(&st[64 + t], q);
    }
}

// ------- combine + xsum fused, BN finalize inline, split-h output ------------
// thread t: pair q = t&31 (channels 2q,2q+1), half = t>>5 (rows 32*half..+31)
__global__ void __launch_bounds__(64)
k_combine_xsum(const float* __restrict__ Y, uint4* __restrict__ hout, int store_h,
               const float* __restrict__ stA, const float* __restrict__ stS,
               const float* __restrict__ bng, const float* __restrict__ bnb,
               const float* __restrict__ bnsg, const float* __restrict__ bnsb) {
    int n  = blockIdx.x & (NN - 1);
    int sg = blockIdx.x >> 9;
    int t  = threadIdx.x;
    int q  = t & 31, half = t >> 5;
    int c0 = 2 * q, c1 = c0 + 1;

    float mean0 = stA[c0] * (1.0f / (float)NT);
    float var0  = stA[64 + c0] * (1.0f / (float)NT) - mean0 * mean0;
    float scl0  = bng[c0] * rsqrtf(var0 + 1e-5f);
    float sh0   = bnb[c0] - mean0 * scl0;
    float mean1 = stA[c1] * (1.0f / (float)NT);
    float var1  = stA[64 + c1] * (1.0f / (float)NT) - mean1 * mean1;
    float scl1  = bng[c1] * rsqrtf(var1 + 1e-5f);
    float sh1   = bnb[c1] - mean1 * scl1;

    float ms0 = stS[c0] * (1.0f / (float)NN);
    float vs0 = stS[64 + c0] * (1.0f / (float)NN) - ms0 * ms0;
    float ss0 = bnsg[c0] * rsqrtf(vs0 + 1e-5f);
    float ms1 = stS[c1] * (1.0f / (float)NN);
    float vs1 = stS[64 + c1] * (1.0f / (float)NN) - ms1 * ms1;
    float ss1 = bnsg[c1] * rsqrtf(vs1 + 1e-5f);
    float2 y2v = reinterpret_cast<const float2*>(g_y2)[n * 32 + q];
    float a20 = y2v.x * ss0 + (bnsb[c0] - ms0 * ss0) + sh0;
    float a21 = y2v.y * ss1 + (bnsb[c1] - ms1 * ss1) + sh1;

    const float2* Y2 = reinterpret_cast<const float2*>(Y);
    uint2* H2 = reinterpret_cast<uint2*>(hout);
    float s0 = 0.f, s1 = 0.f;
#pragma unroll 4
    for (int j = 0; j < 32; j++) {
        int row = sg * 64 + half * 32 + j;
        size_t i = ((size_t)row * NN + n) * 32 + q;
        float2 yv = Y2[i];
        float v0 = fmaxf(yv.x * scl0 + a20, 0.f);
        float v1 = fmaxf(yv.y * scl1 + a21, 0.f);
        if (store_h) {
            uint32_t hi, lo;
            split2(v0, v1, hi, lo);
            H2[i] = make_uint2(hi, lo);
        }
        s0 += v0; s1 += v1;
    }
    reinterpret_cast<float2*>(g_xpart)[((sg * 2 + half) * NN + n) * 32 + q] =
        make_float2(s0 * (1.0f / 512.0f), s1 * (1.0f / 512.0f));
}

// ------------------------- xsum partials of raw x (prologue only) -----------
__global__ void k_xsum_partial(const float* __restrict__ x) {
    int n  = blockIdx.x & (NN - 1);
    int sg = blockIdx.x >> 9;
    int t  = threadIdx.x;
    int q  = t & 31, half = t >> 5;
    const float2* X2 = reinterpret_cast<const float2*>(x);
    float s0 = 0.f, s1 = 0.f;
#pragma unroll 4
    for (int j = 0; j < 32; j++) {
        int row = sg * 64 + half * 32 + j;
        float2 v = X2[((size_t)row * NN + n) * 32 + q];
        s0 += v.x; s1 += v.y;
    }
    reinterpret_cast<float2*>(g_xpart)[((sg * 2 + half) * NN + n) * 32 + q] =
        make_float2(s0 * (1.0f / 512.0f), s1 * (1.0f / 512.0f));
}

// ------------------------- small graph scatter (reads partials) -------------
__global__ void k_scatter_s(const int* __restrict__ src, const int* __restrict__ dst,
                            float* __restrict__ aggs) {
    int t = blockIdx.x * blockDim.x + threadIdx.x;
    int e = t >> 6, c = t & 63;
    if (e < EO) {
        int sidx = src[e] * D + c;
        float v = 0.f;
#pragma unroll
        for (int q16 = 0; q16 < 16; q16++) v += g_xpart[q16 * NN * D + sidx];
        atomicAdd(&aggs[dst[e] * D + c], v);
    }
}

// ------------------------- final head: log_softmax + MLP -------------------
__global__ void k_final(const float* __restrict__ W1, const float* __restrict__ b1,
                        const float* __restrict__ W2, const float* __restrict__ b2,
                        float* __restrict__ out) {
    __shared__ float z[64];
    __shared__ float hid[128];
    __shared__ float red[2];
    int n = blockIdx.x, t = threadIdx.x;
    if (t < 64) {
        float v = 0.f;
#pragma unroll
        for (int q16 = 0; q16 < 16; q16++) v += g_xpart[q16 * NN * D + n * D + t];
        z[t] = v;
    }
    __syncthreads();
    if (t == 0) {
        float m = -1e30f;
        for (int k = 0; k < 64; k++) m = fmaxf(m, z[k]);
        float se = 0.f;
        for (int k = 0; k < 64; k++) se += expf(z[k] - m);
        red[0] = m;
        red[1] = logf(se);
    }
    __syncthreads();
    float m = red[0], ls = red[1];
    float acc = b1[t];
    for (int k = 0; k < 64; k++) acc += (z[k] - m - ls) * W1[t * 64 + k];
    hid[t] = fmaxf(acc, 0.f);
    __syncthreads();
    if (t < 10) {
        float o = b2[t];
        for (int k = 0; k < 128; k++) o += hid[k] * W2[t * 128 + k];
        out[n * 10 + t] = o;
    }
}

// ------------------------- launcher -----------------------------------------
extern "C" void kernel_launch(void* const* d_in, const int* in_sizes, int n_in,
                              void* d_out, int out_size) {
    const float* x      = (const float*)d_in[0];
    const float* Wrel   = (const float*)d_in[1];
    const float* brel   = (const float*)d_in[2];
    const float* Wroot  = (const float*)d_in[3];
    const float* bng    = (const float*)d_in[4];
    const float* bnb    = (const float*)d_in[5];
    const float* Wrel_s = (const float*)d_in[6];
    const float* brel_s = (const float*)d_in[7];
    const float* Wroot_s= (const float*)d_in[8];
    const float* bnsg   = (const float*)d_in[9];
    const float* bnsb   = (const float*)d_in[10];
    const float* W1     = (const float*)d_in[11];
    const float* b1     = (const float*)d_in[12];
    const float* W2     = (const float*)d_in[13];
    const float* b2     = (const float*)d_in[14];
    const int*   ei     = (const int*)d_in[15];
    const int*   oe     = (const int*)d_in[16];
    float*       out    = (float*)d_out;

    cudaFuncSetAttribute(k_gemm_mma,
                         cudaFuncAttributeMaxDynamicSharedMemorySize, SM_MMA_BYTES);

    void *p_cnt, *p_hX, *p_hA, *p_hB, *p_Y, *p_agg, *p_wsplit;
    void *p_aggsB, *p_y2, *p_stAB, *p_stSB;
    cudaGetSymbolAddress(&p_cnt, g_cnt);
    cudaGetSymbolAddress(&p_hX, g_hX);
    cudaGetSymbolAddress(&p_hA, g_hA);
    cudaGetSymbolAddress(&p_hB, g_hB);
    cudaGetSymbolAddress(&p_Y, g_Y);
    cudaGetSymbolAddress(&p_agg, g_agg);
    cudaGetSymbolAddress(&p_wsplit, g_wsplit);
    cudaGetSymbolAddress(&p_aggsB, g_aggsB);
    cudaGetSymbolAddress(&p_y2, g_y2);
    cudaGetSymbolAddress(&p_stAB, g_stAB);
    cudaGetSymbolAddress(&p_stSB, g_stSB);

    // ---- CSR build ----
    cudaMemsetAsync(p_cnt, 0, NT * sizeof(int));
    k_hist<<<E_SUB / 256, 256>>>(ei + E_SUB);
    k_bsum<<<256, 256>>>();
    k_scanb<<<1, 256>>>();
    k_scanlocal<<<256, 256>>>();
    k_scatter<<<E_SUB / 256, 256>>>(ei, ei + E_SUB);

    // ---- prologue: conversions, zeros, xsum partials of raw x ----
    cudaMemsetAsync(p_stAB, 0, LAYERS * 2 * D * sizeof(float));
    cudaMemsetAsync(p_stSB, 0, LAYERS * 2 * D * sizeof(float));
    cudaMemsetAsync(p_aggsB, 0, LAYERS * NN * D * sizeof(float));
    k_split_x<<<NT * 16 / 256, 256>>>(x);
    k_wconv<<<LAYERS * 2 * 64 * 16 / 256, 256>>>(Wrel, Wroot);
    k_xsum_partial<<<NN * 8, 64>>>(x);

    const uint4* hsrc = (const uint4*)p_hX;
    uint4* bufs[2] = { (uint4*)p_hA, (uint4*)p_hB };

    for (int i = 0; i < LAYERS; i++) {
        uint4* hdst = bufs[i & 1];
        float* stA = (float*)p_stAB + i * 2 * D;
        float* stS = (float*)p_stSB + i * 2 * D;
        float* aggs = (float*)p_aggsB + i * NN * D;

        // edge aggregation over split h
        k_gather<<<(NT * 32) / 256, 256>>>(hsrc);

        // big dual GEMM on tensor cores (pre-split operands), fused BN stats
        k_gemm_mma<<<NT / 128, 256, SM_MMA_BYTES>>>((const uint4*)p_agg, hsrc,
                                  (const uint4*)p_wsplit + i * 2048,
                                  brel + i * 64, (float*)p_Y, stA);

        // subgraph-level path (xpart holds partial means of hsrc)
        k_scatter_s<<<(EO * 64) / 256, 256>>>(oe, oe + EO, aggs);
        k_gemmR<<<NN / 64, 256>>>((const float*)aggs,
                                  Wrel_s + i * 4096, Wroot_s + i * 4096, brel_s + i * 64,
                                  (float*)p_y2, stS);

        // combine (BN finalize inline) -> split h_{i+1}, xpart(h_{i+1})
        k_combine_xsum<<<NN * 8, 64>>>((const float*)p_Y, hdst,
                                       (i < LAYERS - 1) ? 1 : 0,
                                       stA, stS,
                                       bng + i * 64, bnb + i * 64,
                                       bnsg + i * 64, bnsb + i * 64);

        hsrc = hdst;
    }

    // readout: xpart holds partial means of final h
    k_final<<<NN, 128>>>(W1, b1, W2, b2, out);
}

// round 17
// speedup vs baseline: 1.0731x; 1.0731x over previous
#include <cuda_runtime.h>
#include <cuda_bf16.h>
#include <cstdint>
#include <math.h>

#define NT      262144      // total nodes (512 subgraphs x 512 nodes)
#define NN      512         // nodes per subgraph / original graph
#define E_SUB   2097152     // edges in union-of-subgraphs graph
#define EO      8192        // edges in original graph
#define D       64          // emb dim
#define LAYERS  4

#define AP      36                      // word pitch (conflict-free)
#define WW_WORDS (64 * AP)              // 2304 words per W sub-tile

// ------------------------- device scratch (no cudaMalloc allowed) ----------
__device__ __align__(16) float g_hA[(size_t)NT * D];
__device__ __align__(16) float g_hB[(size_t)NT * D];
__device__ __align__(16) float g_Y[(size_t)NT * D];
__device__ __align__(16) float g_agg[(size_t)NT * D];

__device__ __align__(16) uint4 g_wsplit[LAYERS * 2 * 64 * 16]; // pre-split W

__device__ __align__(16) float g_xpart[8 * NN * D];      // xsum partials
__device__ __align__(16) float g_aggsB[LAYERS * NN * D]; // per-layer small agg
__device__ __align__(16) float g_y2[NN * D];

__device__ __align__(16) float g_stAB[LAYERS * 2 * D];
__device__ __align__(16) float g_stSB[LAYERS * 2 * D];

__device__ int g_cnt[NT];
__device__ int g_rowptr[NT + 1];
__device__ int g_bsum[256];
__device__ int g_csrsrc[E_SUB];

// ------------------------- CSR build ---------------------------------------
__global__ void k_hist(const int* __restrict__ dst) {
    int e = blockIdx.x * blockDim.x + threadIdx.x;
    if (e < E_SUB) atomicAdd(&g_cnt[dst[e]], 1);
}

__global__ void k_bsum() {
    __shared__ int sh[256];
    int b = blockIdx.x, t = threadIdx.x;
    int base = b * 1024 + t * 4;
    int v = g_cnt[base] + g_cnt[base + 1] + g_cnt[base + 2] + g_cnt[base + 3];
    sh[t] = v;
    __syncthreads();
    for (int off = 128; off > 0; off >>= 1) {
        if (t < off) sh[t] += sh[t + off];
        __syncthreads();
    }
    if (t == 0) g_bsum[b] = sh[0];
}

__global__ void k_scanb() {
    __shared__ int sh[256];
    int t = threadIdx.x;
    int orig = g_bsum[t];
    sh[t] = orig;
    __syncthreads();
    for (int off = 1; off < 256; off <<= 1) {
        int v = (t >= off) ? sh[t - off] : 0;
        __syncthreads();
        sh[t] += v;
        __syncthreads();
    }
    g_bsum[t] = sh[t] - orig;   // exclusive
}

__global__ void k_scanlocal() {
    __shared__ int sh[256];
    int b = blockIdx.x, t = threadIdx.x;
    int base = (b * 256 + t) * 4;
    int c0 = g_cnt[base], c1 = g_cnt[base + 1], c2 = g_cnt[base + 2], c3 = g_cnt[base + 3];
    int tsum = c0 + c1 + c2 + c3;
    sh[t] = tsum;
    __syncthreads();
    for (int off = 1; off < 256; off <<= 1) {
        int v = (t >= off) ? sh[t - off] : 0;
        __syncthreads();
        sh[t] += v;
        __syncthreads();
    }
    int excl = sh[t] - tsum + g_bsum[b];
    int e0 = excl, e1 = e0 + c0, e2 = e1 + c1, e3 = e2 + c2;
    g_rowptr[base] = e0; g_rowptr[base + 1] = e1;
    g_rowptr[base + 2] = e2; g_rowptr[base + 3] = e3;
    g_cnt[base] = e0; g_cnt[base + 1] = e1;
    g_cnt[base + 2] = e2; g_cnt[base + 3] = e3;
    if (b == 255 && t == 255) g_rowptr[NT] = E_SUB;
}

__global__ void k_scatter(const int* __restrict__ src, const int* __restrict__ dst) {
    int e = blockIdx.x * blockDim.x + threadIdx.x;
    if (e < E_SUB) {
        int pos = atomicAdd(&g_cnt[dst[e]], 1);
        g_csrsrc[pos] = src[e];
    }
}

// ------------------------- edge aggregation (atomic-free, fp32) -------------
__global__ void k_gather(const float* __restrict__ h) {
    int gw = (blockIdx.x * blockDim.x + threadIdx.x) >> 5;
    int lane = threadIdx.x & 31;
    if (gw >= NT) return;
    int s = g_rowptr[gw], e = g_rowptr[gw + 1];
    const float2* h2 = reinterpret_cast<const float2*>(h);
    float2 a = make_float2(0.f, 0.f), b = make_float2(0.f, 0.f);
    int i = s;
    for (; i + 1 < e; i += 2) {
        int s0 = g_csrsrc[i], s1 = g_csrsrc[i + 1];
        float2 v0 = h2[(size_t)s0 * 32 + lane];
        float2 v1 = h2[(size_t)s1 * 32 + lane];
        a.x += v0.x; a.y += v0.y;
        b.x += v1.x; b.y += v1.y;
    }
    if (i < e) {
        int s0 = g_csrsrc[i];
        float2 v0 = h2[(size_t)s0 * 32 + lane];
        a.x += v0.x; a.y += v0.y;
    }
    reinterpret_cast<float2*>(g_agg)[(size_t)gw * 32 + lane] =
        make_float2(a.x + b.x, a.y + b.y);
}

// ---------------- bf16 split helpers ----------------------------------------
__device__ __forceinline__ void split2(float x, float y, uint32_t& hi, uint32_t& lo) {
    __nv_bfloat16 hx = __float2bfloat16_rn(x);
    __nv_bfloat16 hy = __float2bfloat16_rn(y);
    __nv_bfloat162 hp = __halves2bfloat162(hx, hy);
    hi = *reinterpret_cast<uint32_t*>(&hp);
    __nv_bfloat162 lp = __floats2bfloat162_rn(
        x - __bfloat162float(hx), y - __bfloat162float(hy));
    lo = *reinterpret_cast<uint32_t*>(&lp);
}

__device__ __forceinline__ void mma_bf16(float* c, uint32_t a0, uint32_t a1,
                                         uint32_t a2, uint32_t a3,
                                         uint32_t b0, uint32_t b1) {
    asm volatile(
        "mma.sync.aligned.m16n8k16.row.col.f32.bf16.bf16.f32 "
        "{%0,%1,%2,%3}, {%4,%5,%6,%7}, {%8,%9}, {%0,%1,%2,%3};"
        : "+f"(c[0]), "+f"(c[1]), "+f"(c[2]), "+f"(c[3])
        : "r"(a0), "r"(a1), "r"(a2), "r"(a3), "r"(b0), "r"(b1));
}

// ---- pre-split W once: layout [l][p][row 64][16 uint4] (hi01,lo01,hi23,lo23)
__global__ void k_wconv(const float* __restrict__ Wrel, const float* __restrict__ Wroot) {
    int task = blockIdx.x * blockDim.x + threadIdx.x;     // < LAYERS*2*64*16
    int f = task & 15, r = (task >> 4) & 63;
    int p = (task >> 10) & 1, l = task >> 11;
    const float* W = (p ? Wroot : Wrel) + l * 4096;
    float4 v = reinterpret_cast<const float4*>(W)[r * 16 + f];
    uint32_t h0, l0, h1, l1;
    split2(v.x, v.y, h0, l0);
    split2(v.z, v.w, h1, l1);
    g_wsplit[task] = make_uint4(h0, l0, h1, l1);
}

// -------- big dual GEMM: A fragments straight from L2, W in smem ------------
// Y[r][c] = A0[r]@W0[c] + A1[r]@W1[c] + bias[c];  fused BN stats.
__global__ void __launch_bounds__(256)
k_gemm_mma(const float* __restrict__ A0, const float* __restrict__ A1,
           const uint4* __restrict__ Wp,       // [2][64][16] pre-split
           const float* __restrict__ bias, float* __restrict__ Y,
           float* __restrict__ st) {
    __shared__ uint32_t Ww[4 * WW_WORDS];       // Wh0 Wl0 Wh1 Wl1 (pitched AP)
    __shared__ float bias_s[64];

    int t = threadIdx.x;
    int w = t >> 5, lane = t & 31;
    int g = lane >> 2, tg = lane & 3;
    int row0 = blockIdx.x * 128;

    if (t < 64) bias_s[t] = bias[t];

    // ---- W tiles (pre-split, pure copy) ----
    for (int p = 0; p < 2; p++) {
        const uint4* src = Wp + p * 1024;
        uint32_t* hb = Ww + (2 * p) * WW_WORDS;
        uint32_t* lb = hb + WW_WORDS;
#pragma unroll
        for (int it = 0; it < 4; it++) {
            int task = it * 256 + t;        // 1024 tasks = 64 rows x 16 uint4
            int r = task >> 4, f = task & 15;
            uint4 v = src[r * 16 + f];
            hb[r * AP + 2 * f]     = v.x;
            lb[r * AP + 2 * f]     = v.y;
            hb[r * AP + 2 * f + 1] = v.z;
            lb[r * AP + 2 * f + 1] = v.w;
        }
    }
    __syncthreads();

    // ---- warp tile: 16 rows x 64 cols; acc[j] = m16n8 fragment ----
    float acc[8][4];
#pragma unroll
    for (int j = 0; j < 8; j++)
#pragma unroll
        for (int i = 0; i < 4; i++) acc[j][i] = 0.f;

    int rowA = row0 + w * 16 + g;       // fragment row pair (rowA, rowA+8)
#pragma unroll
    for (int p = 0; p < 2; p++) {
        const float2* Aa = reinterpret_cast<const float2*>(
            (p ? A1 : A0) + (size_t)rowA * D);
        const float2* Ab = Aa + 8 * 32;     // row +8
        const uint32_t* Wh_ = Ww + (2 * p) * WW_WORDS;
        const uint32_t* Wl_ = Wh_ + WW_WORDS;
#pragma unroll
        for (int ks = 0; ks < 4; ks++) {
            int o = ks * 8 + tg;
            float2 va0 = Aa[o],     vb0 = Ab[o];
            float2 va4 = Aa[o + 4], vb4 = Ab[o + 4];
            uint32_t ah0, al0, ah1, al1, ah2, al2, ah3, al3;
            split2(va0.x, va0.y, ah0, al0);
            split2(vb0.x, vb0.y, ah1, al1);
            split2(va4.x, va4.y, ah2, al2);
            split2(vb4.x, vb4.y, ah3, al3);
#pragma unroll
            for (int j = 0; j < 8; j++) {
                int wb = (j * 8 + g) * AP + o;
                uint32_t bh0 = Wh_[wb], bh1 = Wh_[wb + 4];
                uint32_t bl0 = Wl_[wb], bl1 = Wl_[wb + 4];
                mma_bf16(acc[j], ah0, ah1, ah2, ah3, bh0, bh1);
                mma_bf16(acc[j], al0, al1, al2, al3, bh0, bh1);
                mma_bf16(acc[j], ah0, ah1, ah2, ah3, bl0, bl1);
            }
        }
    }

    // ---- epilogue: bias, write Y, BN stat partials ----
    float ps0[8], ps1[8], pq0[8], pq1[8];
    int r0g = rowA;
#pragma unroll
    for (int j = 0; j < 8; j++) {
        int c0 = j * 8 + 2 * tg;
        float b0 = bias_s[c0], b1 = bias_s[c0 + 1];
        float y00 = acc[j][0] + b0, y01 = acc[j][1] + b1;
        float y10 = acc[j][2] + b0, y11 = acc[j][3] + b1;
        *reinterpret_cast<float2*>(&Y[(size_t)r0g * D + c0]) = make_float2(y00, y01);
        *reinterpret_cast<float2*>(&Y[(size_t)(r0g + 8) * D + c0]) = make_float2(y10, y11);
        ps0[j] = y00 + y10; ps1[j] = y01 + y11;
        pq0[j] = y00 * y00 + y10 * y10;
        pq1[j] = y01 * y01 + y11 * y11;
    }

    __syncthreads();                                  // W smem now free
    float* redS = reinterpret_cast<float*>(Ww);       // [64][72]
    float* redQ = redS + 64 * 72;                     // total 36864B = W area
    int grp = w * 8 + g;
#pragma unroll
    for (int j = 0; j < 8; j++) {
        int c0 = j * 8 + 2 * tg;
        *reinterpret_cast<float2*>(&redS[grp * 72 + c0]) = make_float2(ps0[j], ps1[j]);
        *reinterpret_cast<float2*>(&redQ[grp * 72 + c0]) = make_float2(pq0[j], pq1[j]);
    }
    __syncthreads();
    if (t < 64) {
        float s = 0.f, q = 0.f;
#pragma unroll 4
        for (int k = 0; k < 64; k++) {
            s += redS[k * 72 + t];
            q += redQ[k * 72 + t];
        }
        atomicAdd(&st[t], s);
        atomicAdd(&st[64 + t], q);
    }
}

// ------------------------- small dual GEMM (scalar, fused stats) ------------
// A1 = sum of the 8 xsum partials in g_xpart.
__global__ void __launch_bounds__(256)
k_gemmR(const float* __restrict__ A0,
        const float* __restrict__ W0, const float* __restrict__ W1v,
        const float* __restrict__ bias, float* __restrict__ Y,
        float* __restrict__ st) {
    __shared__ __align__(16) float sA[64][65];
    __shared__ __align__(16) float sW[64][68];
    int t  = threadIdx.x;
    int tx = t & 15, ty = t >> 4;
    int row0 = blockIdx.x * 64;
    int cc = t & 63, rb = t >> 6;

    float acc[4][4];
#pragma unroll
    for (int i = 0; i < 4; i++)
#pragma unroll
        for (int j = 0; j < 4; j++) acc[i][j] = 0.f;

    for (int p = 0; p < 2; p++) {
        const float* W = p ? W1v : W0;
#pragma unroll
        for (int j = 0; j < 16; j++) {
            int r = rb + j * 4;
            float a;
            if (p == 0) {
                a = A0[(size_t)(row0 + r) * D + cc];
            } else {
                a = 0.f;
#pragma unroll
                for (int q8 = 0; q8 < 8; q8++)
                    a += g_xpart[q8 * NN * D + (row0 + r) * D + cc];
            }
            sA[cc][r] = a;
        }
#pragma unroll
        for (int j = 0; j < 16; j++) {
            int ci = rb + j * 4;
            sW[cc][ci] = W[ci * D + cc];
        }
        __syncthreads();
#pragma unroll
        for (int k = 0; k < 64; k++) {
            float4 bv = *reinterpret_cast<const float4*>(&sW[k][tx * 4]);
            float a0 = sA[k][ty * 4 + 0];
            float a1 = sA[k][ty * 4 + 1];
            float a2 = sA[k][ty * 4 + 2];
            float a3 = sA[k][ty * 4 + 3];
            acc[0][0] += a0 * bv.x; acc[0][1] += a0 * bv.y; acc[0][2] += a0 * bv.z; acc[0][3] += a0 * bv.w;
            acc[1][0] += a1 * bv.x; acc[1][1] += a1 * bv.y; acc[1][2] += a1 * bv.z; acc[1][3] += a1 * bv.w;
            acc[2][0] += a2 * bv.x; acc[2][1] += a2 * bv.y; acc[2][2] += a2 * bv.z; acc[2][3] += a2 * bv.w;
            acc[3][0] += a3 * bv.x; acc[3][1] += a3 * bv.y; acc[3][2] += a3 * bv.z; acc[3][3] += a3 * bv.w;
        }
        __syncthreads();
    }

    float4 bb = *reinterpret_cast<const float4*>(&bias[tx * 4]);
    float bcol[4] = { bb.x, bb.y, bb.z, bb.w };
    float ls[4] = {0.f, 0.f, 0.f, 0.f};
    float lq[4] = {0.f, 0.f, 0.f, 0.f};
#pragma unroll
    for (int jr = 0; jr < 4; jr++) {
        float y0 = acc[jr][0] + bcol[0];
        float y1 = acc[jr][1] + bcol[1];
        float y2 = acc[jr][2] + bcol[2];
        float y3 = acc[jr][3] + bcol[3];
        ls[0] += y0; ls[1] += y1; ls[2] += y2; ls[3] += y3;
        lq[0] += y0 * y0; lq[1] += y1 * y1; lq[2] += y2 * y2; lq[3] += y3 * y3;
        int r = row0 + ty * 4 + jr;
        *reinterpret_cast<float4*>(&Y[(size_t)r * D + tx * 4]) =
            make_float4(y0, y1, y2, y3);
    }

    float* rs = &sA[0][0];
    float* rq = rs + 1024;
#pragma unroll
    for (int j = 0; j < 4; j++) {
        rs[ty * 64 + tx * 4 + j] = ls[j];
        rq[ty * 64 + tx * 4 + j] = lq[j];
    }
    __syncthreads();
    if (t < 64) {
        float s = 0.f, q = 0.f;
#pragma unroll
        for (int g = 0; g < 16; g++) {
            s += rs[g * 64 + t];
            q += rq[g * 64 + t];
        }
        atomicAdd(&st[t], s);
        atomicAdd(&st[64 + t], q);
    }
}

// ------- combine + xsum fused, BN finalize inline ----------------------------
__global__ void __launch_bounds__(64)
k_combine_xsum(const float* __restrict__ Y, float* __restrict__ h, int store_h,
               const float* __restrict__ stA, const float* __restrict__ stS,
               const float* __restrict__ bng, const float* __restrict__ bnb,
               const float* __restrict__ bnsg, const float* __restrict__ bnsb) {
    int n  = blockIdx.x & (NN - 1);
    int sg = blockIdx.x >> 9;
    int c  = threadIdx.x;

    float mean = stA[c] * (1.0f / (float)NT);
    float var  = stA[64 + c] * (1.0f / (float)NT) - mean * mean;
    float scl  = bng[c] * rsqrtf(var + 1e-5f);
    float shift = bnb[c] - mean * scl;

    float mean_s = stS[c] * (1.0f / (float)NN);
    float var_s  = stS[64 + c] * (1.0f / (float)NN) - mean_s * mean_s;
    float scl_s  = bnsg[c] * rsqrtf(var_s + 1e-5f);
    float a2 = g_y2[n * D + c] * scl_s + (bnsb[c] - mean_s * scl_s) + shift;

    float s0 = 0.f, s1 = 0.f;
#pragma unroll 4
    for (int j = 0; j < 64; j += 2) {
        size_t i0 = ((size_t)(sg * 64 + j)     * NN + n) * D + c;
        size_t i1 = ((size_t)(sg * 64 + j + 1) * NN + n) * D + c;
        float v0 = fmaxf(Y[i0] * scl + a2, 0.f);
        float v1 = fmaxf(Y[i1] * scl + a2, 0.f);
        if (store_h) { h[i0] = v0; h[i1] = v1; }
        s0 += v0; s1 += v1;
    }
    g_xpart[(sg * NN + n) * D + c] = (s0 + s1) * (1.0f / 512.0f);
}

// ------------------------- xsum partials of raw x (prologue only) -----------
__global__ void k_xsum_partial(const float* __restrict__ Y) {
    int n  = blockIdx.x & (NN - 1);
    int sg = blockIdx.x >> 9;
    int c  = threadIdx.x;
    float a0 = 0.f, a1 = 0.f;
#pragma unroll 4
    for (int j = 0; j < 64; j += 2) {
        int s = sg * 64 + j;
        a0 += Y[((size_t)(s + 0) * NN + n) * D + c];
        a1 += Y[((size_t)(s + 1) * NN + n) * D + c];
    }
    g_xpart[(sg * NN + n) * D + c] = (a0 + a1) * (1.0f / 512.0f);
}

// ------------------------- small graph scatter (reads partials) -------------
__global__ void k_scatter_s(const int* __restrict__ src, const int* __restrict__ dst,
                            float* __restrict__ aggs) {
    int t = blockIdx.x * blockDim.x + threadIdx.x;
    int e = t >> 6, c = t & 63;
    if (e < EO) {
        int sidx = src[e] * D + c;
        float v = 0.f;
#pragma unroll
        for (int q8 = 0; q8 < 8; q8++) v += g_xpart[q8 * NN * D + sidx];
        atomicAdd(&aggs[dst[e] * D + c], v);
    }
}

// ------------------------- final head: log_softmax + MLP -------------------
__global__ void k_final(const float* __restrict__ W1, const float* __restrict__ b1,
                        const float* __restrict__ W2, const float* __restrict__ b2,
                        float* __restrict__ out) {
    __shared__ float z[64];
    __shared__ float hid[128];
    __shared__ float red[2];
    int n = blockIdx.x, t = threadIdx.x;
    if (t < 64) {
        float v = 0.f;
#pragma unroll
        for (int q8 = 0; q8 < 8; q8++) v += g_xpart[q8 * NN * D + n * D + t];
        z[t] = v;
    }
    __syncthreads();
    if (t == 0) {
        float m = -1e30f;
        for (int k = 0; k < 64; k++) m = fmaxf(m, z[k]);
        float se = 0.f;
        for (int k = 0; k < 64; k++) se += expf(z[k] - m);
        red[0] = m;
        red[1] = logf(se);
    }
    __syncthreads();
    float m = red[0], ls = red[1];
    float acc = b1[t];
    for (int k = 0; k < 64; k++) acc += (z[k] - m - ls) * W1[t * 64 + k];
    hid[t] = fmaxf(acc, 0.f);
    __syncthreads();
    if (t < 10) {
        float o = b2[t];
        for (int k = 0; k < 128; k++) o += hid[k] * W2[t * 128 + k];
        out[n * 10 + t] = o;
    }
}

// ------------------------- launcher -----------------------------------------
extern "C" void kernel_launch(void* const* d_in, const int* in_sizes, int n_in,
                              void* d_out, int out_size) {
    const float* x      = (const float*)d_in[0];
    const float* Wrel   = (const float*)d_in[1];
    const float* brel   = (const float*)d_in[2];
    const float* Wroot  = (const float*)d_in[3];
    const float* bng    = (const float*)d_in[4];
    const float* bnb    = (const float*)d_in[5];
    const float* Wrel_s = (const float*)d_in[6];
    const float* brel_s = (const float*)d_in[7];
    const float* Wroot_s= (const float*)d_in[8];
    const float* bnsg   = (const float*)d_in[9];
    const float* bnsb   = (const float*)d_in[10];
    const float* W1     = (const float*)d_in[11];
    const float* b1     = (const float*)d_in[12];
    const float* W2     = (const float*)d_in[13];
    const float* b2     = (const float*)d_in[14];
    const int*   ei     = (const int*)d_in[15];
    const int*   oe     = (const int*)d_in[16];
    float*       out    = (float*)d_out;

    void *p_cnt, *p_hA, *p_hB, *p_Y, *p_agg, *p_wsplit;
    void *p_aggsB, *p_y2, *p_stAB, *p_stSB;
    cudaGetSymbolAddress(&p_cnt, g_cnt);
    cudaGetSymbolAddress(&p_hA, g_hA);
    cudaGetSymbolAddress(&p_hB, g_hB);
    cudaGetSymbolAddress(&p_Y, g_Y);
    cudaGetSymbolAddress(&p_agg, g_agg);
    cudaGetSymbolAddress(&p_wsplit, g_wsplit);
    cudaGetSymbolAddress(&p_aggsB, g_aggsB);
    cudaGetSymbolAddress(&p_y2, g_y2);
    cudaGetSymbolAddress(&p_stAB, g_stAB);
    cudaGetSymbolAddress(&p_stSB, g_stSB);

    // ---- CSR build ----
    cudaMemsetAsync(p_cnt, 0, NT * sizeof(int));
    k_hist<<<E_SUB / 256, 256>>>(ei + E_SUB);
    k_bsum<<<256, 256>>>();
    k_scanb<<<1, 256>>>();
    k_scanlocal<<<256, 256>>>();
    k_scatter<<<E_SUB / 256, 256>>>(ei, ei + E_SUB);

    // ---- prologue: W pre-split, zeros, xsum partials of raw x ----
    cudaMemsetAsync(p_stAB, 0, LAYERS * 2 * D * sizeof(float));
    cudaMemsetAsync(p_stSB, 0, LAYERS * 2 * D * sizeof(float));
    cudaMemsetAsync(p_aggsB, 0, LAYERS * NN * D * sizeof(float));
    k_wconv<<<LAYERS * 2 * 64 * 16 / 256, 256>>>(Wrel, Wroot);
    k_xsum_partial<<<NN * 8, 64>>>(x);

    const float* hsrc = x;
    float* bufs[2] = { (float*)p_hA, (float*)p_hB };

    for (int i = 0; i < LAYERS; i++) {
        float* hdst = bufs[i & 1];
        float* stA = (float*)p_stAB + i * 2 * D;
        float* stS = (float*)p_stSB + i * 2 * D;
        float* aggs = (float*)p_aggsB + i * NN * D;

        // edge aggregation over materialized h
        k_gather<<<(NT * 32) / 256, 256>>>(hsrc);

        // big dual GEMM (A direct from L2, W pre-split in smem), fused stats
        k_gemm_mma<<<NT / 128, 256>>>((const float*)p_agg, hsrc,
                                  (const uint4*)p_wsplit + i * 2048,
                                  brel + i * 64, (float*)p_Y, stA);

        // subgraph-level path (xpart holds partial means of hsrc)
        k_scatter_s<<<(EO * 64) / 256, 256>>>(oe, oe + EO, aggs);
        k_gemmR<<<NN / 64, 256>>>((const float*)aggs,
                                  Wrel_s + i * 4096, Wroot_s + i * 4096, brel_s + i * 64,
                                  (float*)p_y2, stS);

        // combine (BN finalize inline) -> h_{i+1}, xpart(h_{i+1})
        k_combine_xsum<<<NN * 8, 64>>>((const float*)p_Y, hdst,
                                       (i < LAYERS - 1) ? 1 : 0,
                                       stA, stS,
                                       bng + i * 64, bnb + i * 64,
                                       bnsg + i * 64, bnsb + i * 64);

        hsrc = hdst;
    }

    // readout: xpart holds partial means of final h
    k_final<<<NN, 128>>>(W1, b1, W2, b2, out);
}